// round 14
// baseline (speedup 1.0000x reference)
#include <cuda_runtime.h>
#include <math.h>

// Problem constants
#define Lc 2048
#define Hc 8
#define Bc 8
#define Sc 128
#define HSc 1024
#define NBLK 256

// ---------------- scratch (device globals) ----------------------------------
__device__ float d_eT[Hc * Lc];       // eT[h][d] = exp(W[d][h])
__device__ float d_zinv[Lc * Hc];     // 1/Z[l][h]
__device__ float d_q[Bc * HSc];
__device__ float d_u[Bc * HSc];
__device__ float d_G[Hc * Lc * Bc];   // G2[h][j][b]
__device__ float d_scores[Bc * Lc];
__device__ int g_cnt;                 // grid barrier counter (zero-init, self-resetting)
__device__ volatile int g_gen;        // grid barrier generation

// f32x2 packed helpers (sm_100+)
__device__ __forceinline__ unsigned long long pack2(float v) {
    unsigned long long r;
    asm("mov.b64 %0, {%1, %1};" : "=l"(r) : "f"(v));
    return r;
}
__device__ __forceinline__ void fma2(unsigned long long& acc,
                                     unsigned long long a, unsigned long long b) {
    asm("fma.rn.f32x2 %0, %1, %2, %0;" : "+l"(acc) : "l"(a), "l"(b));
}
__device__ __forceinline__ float2 unpack2(unsigned long long v) {
    float2 r;
    asm("mov.b64 {%0, %1}, %2;" : "=f"(r.x), "=f"(r.y) : "l"(v));
    return r;
}

// named barrier for a 128-thread half (sub=0: warps 0-3, sub=1: warps 4-7)
__device__ __forceinline__ void half_bar(int sub) {
    asm volatile("bar.sync %0, 128;" :: "r"(1 + sub) : "memory");
}

// software grid barrier (all NBLK blocks co-resident by construction)
__device__ __forceinline__ void grid_sync() {
    __threadfence();
    __syncthreads();
    if (threadIdx.x == 0) {
        int gen = g_gen;
        if (atomicAdd(&g_cnt, 1) == NBLK - 1) {
            g_cnt = 0;
            __threadfence();
            g_gen = gen + 1;
        } else {
            while (g_gen == gen) { __nanosleep(40); }
        }
        __threadfence();
    }
    __syncthreads();
}

// ---------------- the fused persistent kernel --------------------------------
__global__ void __launch_bounds__(256, 2) k_fused(const float* __restrict__ W,
                                                  const float* __restrict__ A,
                                                  const float* __restrict__ x,
                                                  float* __restrict__ out) {
    __shared__ __align__(16) char SM[34816];
    int blk = blockIdx.x;
    int t = threadIdx.x;
    int sub = t >> 7, t128 = t & 127;
    int lane = t & 31;

    // ============ P0: scan (blocks 0..7) + zero everything (blocks 8..255) ==
    if (blk < 8) {
        int h = blk;
        float* wsum = (float*)SM;                     // 8 floats
        float v[8];
        float tot = 0.f;
        #pragma unroll
        for (int k = 0; k < 8; k++) {
            v[k] = expf(W[(t * 8 + k) * Hc + h]);
            tot += v[k];
        }
        int wid = t >> 5;
        float xs = tot;
        #pragma unroll
        for (int o = 1; o < 32; o <<= 1) {
            float y = __shfl_up_sync(0xffffffffu, xs, o);
            if (lane >= o) xs += y;
        }
        if (lane == 31) wsum[wid] = xs;
        __syncthreads();
        float woff = 0.f;
        for (int ww = 0; ww < wid; ww++) woff += wsum[ww];
        float p = xs + woff - tot;                    // exclusive before d = 8t
        #pragma unroll
        for (int k = 0; k < 8; k++) {
            int d = t * 8 + k;
            p += v[k];
            d_eT[h * Lc + d] = v[k];
            d_zinv[d * Hc + h] = 1.f / p;
        }
    } else {
        int gid = (blk - 8) * 256 + t;                // [0, 63488)
        float4 z4 = make_float4(0.f, 0.f, 0.f, 0.f);
        if (gid < 32768) *(float4*)&d_G[gid * 4] = z4;
        if (gid < 8192) { d_q[gid] = 0.f; d_u[gid] = 0.f; }
        if (gid < 16384) d_scores[gid] = 0.f;
        if (gid < 1024)  out[gid] = 0.f;
    }
    grid_sync();

    // ============ P1: q_raw[b][h*S+s] = sum_j e[L-1-j,h] * x[b,j,s] =========
    // 512 items (64 j-chunks of 32 x 8 b), one per 128-thread half.
    {
        float (*se)[256] = (float (*)[256])SM;        // se[sub][jj*8+h]
        int item = 2 * blk + sub;                     // [0,512)
        int jc = item >> 3, b = item & 7;
        int jbase = jc * 32;
        int s = t128;
        for (int i = s; i < 256; i += 128) {
            int jj = i >> 3, h = i & 7;
            se[sub][i] = d_eT[h * Lc + (Lc - 1 - (jbase + jj))];
        }
        half_bar(sub);

        unsigned long long a2[4] = {};
        const float* xp = x + ((size_t)b * Lc + jbase) * Sc + s;
        float xv[32];
        #pragma unroll
        for (int k = 0; k < 32; k++) xv[k] = xp[k * Sc];
        #pragma unroll
        for (int k = 0; k < 32; k++) {
            unsigned long long xd = pack2(xv[k]);
            ulonglong2 e01 = *(const ulonglong2*)&se[sub][k * 8];
            ulonglong2 e23 = *(const ulonglong2*)&se[sub][k * 8 + 4];
            fma2(a2[0], xd, e01.x);
            fma2(a2[1], xd, e01.y);
            fma2(a2[2], xd, e23.x);
            fma2(a2[3], xd, e23.y);
        }
        #pragma unroll
        for (int p = 0; p < 4; p++) {
            float2 v = unpack2(a2[p]);
            atomicAdd(&d_q[b * HSc + (2 * p) * Sc + s], v.x);
            atomicAdd(&d_q[b * HSc + (2 * p + 1) * Sc + s], v.y);
        }
    }
    grid_sync();

    // ============ P2: u[b][e] = sum_d (q[b][d]*zinv_last) * A[d][e] =========
    // 256 items (4 e-chunks x 64 d-chunks of 16), one per block.
    {
        float* sq = (float*)SM;                       // sq[dd*8+b], 128 floats
        int item = blk;
        int ebase = (item & 3) * 256;
        int dbase = (item >> 2) * 16;
        if (t < 128) {
            int dd = t >> 3, b = t & 7;
            int d = dbase + dd;
            sq[t] = d_q[b * HSc + d] * d_zinv[(Lc - 1) * Hc + (d >> 7)];
        }
        __syncthreads();

        int e = ebase + t;
        unsigned long long a2[4] = {};
        const float* Ap = A + (size_t)dbase * HSc + e;
        float av[16];
        #pragma unroll
        for (int k = 0; k < 16; k++) av[k] = Ap[k * HSc];
        #pragma unroll
        for (int k = 0; k < 16; k++) {
            unsigned long long ad = pack2(av[k]);
            ulonglong2 q01 = *(const ulonglong2*)&sq[k * 8];
            ulonglong2 q23 = *(const ulonglong2*)&sq[k * 8 + 4];
            fma2(a2[0], ad, q01.x);
            fma2(a2[1], ad, q01.y);
            fma2(a2[2], ad, q23.x);
            fma2(a2[3], ad, q23.y);
        }
        #pragma unroll
        for (int p = 0; p < 4; p++) {
            float2 v = unpack2(a2[p]);
            atomicAdd(&d_u[(2 * p) * HSc + e], v.x);
            atomicAdd(&d_u[(2 * p + 1) * HSc + e], v.y);
        }
    }
    grid_sync();

    // ============ P3: G2[h][j][b] += sum_{s half} u * x =====================
    // 512 items (32 j-tiles x 2 s-halves x 8 b), two sequential per block.
    {
        float* sxT = (float*)SM;                                  // [64][66]
        unsigned long long (*spart)[32][8] = (unsigned long long (*)[32][8])SM;
        unsigned long long* su2 = (unsigned long long*)(SM + 16896); // [512]
        int w = t >> 5;

        #pragma unroll 1
        for (int it = 0; it < 2; it++) {
            int item = blk + 256 * it;                // [0,512)
            int jt = item & 31, sz = (item >> 5) & 1, b = item >> 6;
            int jbase = jt * 64;
            int s0 = sz * 64;

            int sl = t & 63, jh = t >> 6;
            float xv[16];
            {
                const float* xb = x + ((size_t)b * Lc + jbase) * Sc + s0 + sl;
                #pragma unroll
                for (int r = 0; r < 16; r++) xv[r] = xb[(size_t)(r * 4 + jh) * Sc];
            }
            for (int i = t; i < 512; i += 256) {
                int h = i >> 6, sll = i & 63;
                su2[i] = pack2(d_u[b * HSc + h * Sc + s0 + sll]);
            }
            #pragma unroll
            for (int r = 0; r < 16; r++) sxT[sl * 66 + r * 4 + jh] = xv[r];
            __syncthreads();

            unsigned long long acc[8] = {};
            int sc0 = w * 8;
            #pragma unroll
            for (int si = 0; si < 8; si++) {
                int slc = sc0 + si;
                unsigned long long xvv =
                    *(const unsigned long long*)&sxT[slc * 66 + 2 * lane];
                #pragma unroll
                for (int h = 0; h < 8; h++)
                    fma2(acc[h], xvv, su2[h * 64 + slc]);
            }
            __syncthreads();      // sxT reads done before spart overwrites

            #pragma unroll
            for (int h = 0; h < 8; h++) spart[w][lane][h] = acc[h];
            __syncthreads();

            {
                int jp = t >> 3, h = t & 7;
                float vx = 0.f, vy = 0.f;
                #pragma unroll
                for (int c = 0; c < 8; c++) {
                    float2 p = unpack2(spart[c][jp][h]);
                    vx += p.x; vy += p.y;
                }
                float* gp = d_G + (size_t)h * (Lc * Bc) + (jbase + 2 * jp) * 8 + b;
                atomicAdd(gp,     vx);
                atomicAdd(gp + 8, vy);
            }
            __syncthreads();      // done with SM before next item restages
        }
    }
    grid_sync();

    // ============ P4: Toeplitz causal correlation ===========================
    // 512 items (16 lt x 4 jg x 8 h), one per 128-thread half (named barriers).
    {
        float (*sacc)[4][128][8] = (float (*)[4][128][8])SM;         // [sub]
        float (*se)[256] = (float (*)[256])(SM + 32768);             // [sub]
        int idx = 2 * blk + sub;
        int h = idx & 7, jg = (idx >> 3) & 3, lt = idx >> 5;
        int jt0 = jg * 4;
        if (jt0 <= lt) {
            int jt1 = min(jt0 + 4, lt + 1);
            int lbase = lt * 128;
            int w = t128 >> 5;

            unsigned long long acc[4][4] = {};
            const float* eTh = d_eT + (size_t)h * Lc;
            const float* Gh  = d_G + (size_t)h * Lc * Bc;

            for (int jt = jt0; jt < jt1; jt++) {
                int D0 = lbase - jt * 128;
                half_bar(sub);
                {
                    int d0 = D0 - 127 + t128, d1 = D0 + 1 + t128;
                    se[sub][t128] = (d0 >= 0) ? eTh[d0] : 0.f;
                    se[sub][t128 + 128] = (d1 >= 0) ? eTh[d1] : 0.f;
                }
                half_bar(sub);

                int jb = jt * 128 + w * 32;
                int base_idx = 127 + lane - w * 32;
                #pragma unroll 2
                for (int jj = 0; jj < 32; jj++) {
                    int j = jb + jj;
                    ulonglong2 g01 = *(const ulonglong2*)(Gh + j * 8);
                    ulonglong2 g23 = *(const ulonglong2*)(Gh + j * 8 + 4);
                    int bi = base_idx - jj;
                    #pragma unroll
                    for (int k = 0; k < 4; k++) {
                        unsigned long long ev = pack2(se[sub][bi + 32 * k]);
                        fma2(acc[k][0], ev, g01.x);
                        fma2(acc[k][1], ev, g01.y);
                        fma2(acc[k][2], ev, g23.x);
                        fma2(acc[k][3], ev, g23.y);
                    }
                }
            }

            #pragma unroll
            for (int k = 0; k < 4; k++) {
                float2 p0 = unpack2(acc[k][0]);
                float2 p1 = unpack2(acc[k][1]);
                float2 p2 = unpack2(acc[k][2]);
                float2 p3 = unpack2(acc[k][3]);
                *(float4*)&sacc[sub][w][lane + 32 * k][0] =
                    make_float4(p0.x, p0.y, p1.x, p1.y);
                *(float4*)&sacc[sub][w][lane + 32 * k][4] =
                    make_float4(p2.x, p2.y, p3.x, p3.y);
            }
            half_bar(sub);

            int l = lbase + t128;
            if (l < Lc - 1) {
                float zi = d_zinv[l * Hc + h];
                #pragma unroll
                for (int b = 0; b < 8; b++) {
                    float v = sacc[sub][0][t128][b] + sacc[sub][1][t128][b] +
                              sacc[sub][2][t128][b] + sacc[sub][3][t128][b];
                    atomicAdd(&d_scores[b * Lc + l], v * zi);
                }
            }
        }
    }
    grid_sync();

    // ============ P5: softmax + out =========================================
    // 512 items (64 l-chunks of 32 x 8 b), one per 128-thread half.
    {
        float (*red)[128] = (float (*)[128])SM;       // [sub][128]
        float (*wsm)[32] = (float (*)[32])(SM + 1024);
        int item = 2 * blk + sub;
        int lchunk = item >> 3, b = item & 7;
        int lbase = lchunk * 32;
        const float* sc = d_scores + b * Lc;

        float m = -1e30f;
        for (int l = t128; l < Lc - 1; l += 128) m = fmaxf(m, sc[l]);
        red[sub][t128] = m;
        half_bar(sub);
        for (int o = 64; o > 0; o >>= 1) {
            if (t128 < o) red[sub][t128] = fmaxf(red[sub][t128], red[sub][t128 + o]);
            half_bar(sub);
        }
        float M = red[sub][0];
        half_bar(sub);
        float ss = 0.f;
        for (int l = t128; l < Lc - 1; l += 128) ss += expf(sc[l] - M);
        red[sub][t128] = ss;
        half_bar(sub);
        for (int o = 64; o > 0; o >>= 1) {
            if (t128 < o) red[sub][t128] += red[sub][t128 + o];
            half_bar(sub);
        }
        float sinv = 1.f / red[sub][0];

        if (t128 < 32) {
            int lg = lbase + t128;
            wsm[sub][t128] = (lg < Lc - 1) ? expf(sc[lg] - M) * sinv : 0.f;
        }
        half_bar(sub);

        float acc = 0.f;
        const float* xp = x + ((size_t)b * Lc + lbase) * Sc + t128;
        float xv[32];
        #pragma unroll
        for (int k = 0; k < 32; k++) xv[k] = xp[k * Sc];
        #pragma unroll
        for (int k = 0; k < 32; k++) acc += wsm[sub][k] * xv[k];
        atomicAdd(&out[b * Sc + t128], acc);
    }
}

// ---------------- launch ----------------------------------------------------
extern "C" void kernel_launch(void* const* d_in, const int* in_sizes, int n_in,
                              void* d_out, int out_size) {
    const float *x = nullptr, *W = nullptr, *A = nullptr;
    for (int i = 0; i < n_in; i++) {
        if (in_sizes[i] == Bc * Lc * Sc)      x = (const float*)d_in[i];
        else if (in_sizes[i] == Lc * Hc)      W = (const float*)d_in[i];
        else if (in_sizes[i] == HSc * HSc)    A = (const float*)d_in[i];
    }
    float* out = (float*)d_out;

    k_fused<<<NBLK, 256>>>(W, A, x, out);
}

// round 15
// speedup vs baseline: 1.3343x; 1.3343x over previous
#include <cuda_runtime.h>
#include <math.h>

// Problem constants
#define Lc 2048
#define Hc 8
#define Bc 8
#define Sc 128
#define HSc 1024

// ---------------- scratch (device globals) ----------------------------------
__device__ float d_eT[Hc * Lc];       // eT[h][d] = exp(W[d][h])
__device__ float d_zinv[Lc * Hc];     // 1/Z[l][h]
__device__ float d_q[Bc * HSc];
__device__ float d_u[Bc * HSc];
__device__ float d_G[Hc * Lc * Bc];   // G2[h][j][b] (accumulated, zeroed in init)
__device__ float d_scores[Bc * Lc];

// f32x2 packed helpers (sm_100+)
__device__ __forceinline__ unsigned long long pack2(float v) {
    unsigned long long r;
    asm("mov.b64 %0, {%1, %1};" : "=l"(r) : "f"(v));
    return r;
}
__device__ __forceinline__ void fma2(unsigned long long& acc,
                                     unsigned long long a, unsigned long long b) {
    asm("fma.rn.f32x2 %0, %1, %2, %0;" : "+l"(acc) : "l"(a), "l"(b));
}
__device__ __forceinline__ float2 unpack2(unsigned long long v) {
    float2 r;
    asm("mov.b64 {%0, %1}, %2;" : "=f"(r.x), "=f"(r.y) : "l"(v));
    return r;
}

// ---------------- K0: init = scan (blocks 0..7) + zero (blocks 8..23) ------
__global__ void __launch_bounds__(1024) k_init(const float* __restrict__ W,
                                               float* __restrict__ out) {
    int blk = blockIdx.x;
    int t = threadIdx.x;
    if (blk < 8) {
        int h = blk;
        float v0 = expf(W[(2 * t) * Hc + h]);
        float v1 = expf(W[(2 * t + 1) * Hc + h]);
        float s = v0 + v1;
        unsigned lane = t & 31, wid = t >> 5;
        float x = s;
        #pragma unroll
        for (int o = 1; o < 32; o <<= 1) {
            float y = __shfl_up_sync(0xffffffffu, x, o);
            if (lane >= (unsigned)o) x += y;
        }
        __shared__ float wsum[32];
        if (lane == 31) wsum[wid] = x;
        __syncthreads();
        if (wid == 0) {
            float ws = wsum[lane];
            #pragma unroll
            for (int o = 1; o < 32; o <<= 1) {
                float y = __shfl_up_sync(0xffffffffu, ws, o);
                if (lane >= (unsigned)o) ws += y;
            }
            wsum[lane] = ws;
        }
        __syncthreads();
        float warp_off = (wid == 0) ? 0.f : wsum[wid - 1];
        float incl = x + warp_off;
        float excl = incl - s;
        d_eT[h * Lc + 2 * t]     = v0;
        d_eT[h * Lc + 2 * t + 1] = v1;
        d_zinv[(2 * t) * Hc + h]     = 1.f / (excl + v0);
        d_zinv[(2 * t + 1) * Hc + h] = 1.f / incl;
    } else {
        int i = (blk - 8) * 1024 + t;
        if (i < Bc * HSc) { d_q[i] = 0.f; d_u[i] = 0.f; }
        if (i < Bc * Lc)  d_scores[i] = 0.f;
        if (i < Bc * Sc)  out[i] = 0.f;
        // zero d_G: 131072 floats = 16384 indices x 8
        float4 z4 = make_float4(0.f, 0.f, 0.f, 0.f);
        *(float4*)&d_G[i * 8]     = z4;
        *(float4*)&d_G[i * 8 + 4] = z4;
    }
}

// ---------------- K1: q_raw[b][h*S+s] = sum_j e[L-1-j,h] * x[b,j,s] --------
// grid (L/32, B) = 512 blocks, block 128 (thread = s). Batch-32 loads.
__global__ void __launch_bounds__(128) k_q(const float* __restrict__ x) {
    int jbase = blockIdx.x * 32;
    int b = blockIdx.y;
    int s = threadIdx.x;
    __shared__ __align__(16) float se[32 * 8];   // se[jj][h]
    for (int i = s; i < 32 * 8; i += 128) {
        int jj = i >> 3, h = i & 7;
        se[i] = d_eT[h * Lc + (Lc - 1 - (jbase + jj))];
    }
    __syncthreads();

    unsigned long long a2[4] = {};
    const float* xp = x + ((size_t)b * Lc + jbase) * Sc + s;
    float xv[32];
    #pragma unroll
    for (int k = 0; k < 32; k++) xv[k] = xp[k * Sc];
    #pragma unroll
    for (int k = 0; k < 32; k++) {
        unsigned long long xd = pack2(xv[k]);
        ulonglong2 e01 = *(const ulonglong2*)&se[k * 8];
        ulonglong2 e23 = *(const ulonglong2*)&se[k * 8 + 4];
        fma2(a2[0], xd, e01.x);
        fma2(a2[1], xd, e01.y);
        fma2(a2[2], xd, e23.x);
        fma2(a2[3], xd, e23.y);
    }
    #pragma unroll
    for (int p = 0; p < 4; p++) {
        float2 v = unpack2(a2[p]);
        atomicAdd(&d_q[b * HSc + (2 * p) * Sc + s], v.x);
        atomicAdd(&d_q[b * HSc + (2 * p + 1) * Sc + s], v.y);
    }
}

// ---------------- K2: u[b][e] = sum_d (q[b][d]*zinv_last) * A[d][e] --------
// grid (4 e-chunks, 32 d-chunks of 32), block 256. Batch-32 A loads.
__global__ void __launch_bounds__(256) k_u(const float* __restrict__ A) {
    int ebase = blockIdx.x * 256;
    int dbase = blockIdx.y * 32;
    int t = threadIdx.x;
    __shared__ __align__(16) float sq[32 * 8];   // sq[dd][b]
    {
        int dd = t >> 3, b = t & 7;
        int d = dbase + dd;
        sq[t] = d_q[b * HSc + d] * d_zinv[(Lc - 1) * Hc + (d >> 7)];
    }
    __syncthreads();

    int e = ebase + t;
    unsigned long long a2[4] = {};
    const float* Ap = A + (size_t)dbase * HSc + e;
    float av[32];
    #pragma unroll
    for (int k = 0; k < 32; k++) av[k] = Ap[k * HSc];
    #pragma unroll
    for (int k = 0; k < 32; k++) {
        unsigned long long ad = pack2(av[k]);
        ulonglong2 q01 = *(const ulonglong2*)&sq[k * 8];
        ulonglong2 q23 = *(const ulonglong2*)&sq[k * 8 + 4];
        fma2(a2[0], ad, q01.x);
        fma2(a2[1], ad, q01.y);
        fma2(a2[2], ad, q23.x);
        fma2(a2[3], ad, q23.y);
    }
    #pragma unroll
    for (int p = 0; p < 4; p++) {
        float2 v = unpack2(a2[p]);
        atomicAdd(&d_u[(2 * p) * HSc + e], v.x);
        atomicAdd(&d_u[(2 * p + 1) * HSc + e], v.y);
    }
}

// ---------------- K3: G2[h][j][b] += sum_{s in half} u[b][h*S+s]*x[b][j][s] -
// s-split: grid (L/64, 2, B), block 256. Batch-16 register staging loads.
__global__ void __launch_bounds__(256) k_G(const float* __restrict__ x) {
    int b = blockIdx.z;
    int sz = blockIdx.y;                 // s-half: 0 or 1
    int jbase = blockIdx.x * 64;
    int t = threadIdx.x, w = t >> 5, lane = t & 31;
    __shared__ __align__(16) char sbuf[64 * 66 * 4];             // 16896 B
    __shared__ __align__(16) unsigned long long su2[8 * 64];     // 4096 B
    float* sxT = (float*)sbuf;                                   // sxT[sl][j], pitch 66
    unsigned long long (*spart)[32][8] =
        (unsigned long long (*)[32][8])sbuf;                     // [warp][jp][h]

    int s0 = sz * 64;

    // stage x transposed: batch-16 explicit loads, then STS
    int sl = t & 63, jh = t >> 6;
    float xv[16];
    {
        const float* xb = x + ((size_t)b * Lc + jbase) * Sc + s0 + sl;
        #pragma unroll
        for (int r = 0; r < 16; r++) xv[r] = xb[(size_t)(r * 4 + jh) * Sc];
    }
    for (int i = t; i < 512; i += 256) {
        int h = i >> 6, sll = i & 63;
        su2[i] = pack2(d_u[b * HSc + h * Sc + s0 + sll]);
    }
    #pragma unroll
    for (int r = 0; r < 16; r++) sxT[sl * 66 + r * 4 + jh] = xv[r];
    __syncthreads();

    // compute: warp w covers sl in [8w, 8w+8); lane = j-pair
    unsigned long long acc[8] = {};
    int sc0 = w * 8;
    #pragma unroll
    for (int si = 0; si < 8; si++) {
        int slc = sc0 + si;
        unsigned long long xvv = *(const unsigned long long*)&sxT[slc * 66 + 2 * lane];
        #pragma unroll
        for (int h = 0; h < 8; h++)
            fma2(acc[h], xvv, su2[h * 64 + slc]);
    }
    __syncthreads();   // sxT reads done before spart overwrites buffer

    #pragma unroll
    for (int h = 0; h < 8; h++) spart[w][lane][h] = acc[h];
    __syncthreads();

    {
        int jp = t >> 3, h = t & 7;
        float vx = 0.f, vy = 0.f;
        #pragma unroll
        for (int c = 0; c < 8; c++) {
            float2 p = unpack2(spart[c][jp][h]);
            vx += p.x; vy += p.y;
        }
        float* gp = d_G + (size_t)h * (Lc * Bc) + (jbase + 2 * jp) * 8 + b;
        atomicAdd(gp,     vx);
        atomicAdd(gp + 8, vy);
    }
}

// ---------------- K4: Toeplitz causal correlation (dominant) ---------------
// jg granularity 2 for balance; heavy-first block order packs the tail wave.
__global__ void __launch_bounds__(128) k_scores() {
    int lt = (int)gridDim.x - 1 - (int)blockIdx.x;
    int jg = blockIdx.y, h = blockIdx.z;
    int jt0 = jg * 2;
    if (jt0 > lt) return;
    int jt1 = min(jt0 + 2, lt + 1);
    int lbase = lt * 128;
    int t = threadIdx.x, w = t >> 5, lane = t & 31;

    unsigned long long acc[4][4] = {};   // [k][b-pair]
    const float* eTh = d_eT + (size_t)h * Lc;
    const float* Gh  = d_G + (size_t)h * Lc * Bc;

    __shared__ __align__(16) float se[256];

    for (int jt = jt0; jt < jt1; jt++) {
        int D0 = lbase - jt * 128;          // >= 0
        __syncthreads();
        {
            int d0 = D0 - 127 + t, d1 = D0 + 1 + t;
            se[t] = (d0 >= 0) ? eTh[d0] : 0.f;
            se[t + 128] = (d1 >= 0) ? eTh[d1] : 0.f;
        }
        __syncthreads();

        int jb = jt * 128 + w * 32;
        int base_idx = 127 + lane - w * 32;
        #pragma unroll 2
        for (int jj = 0; jj < 32; jj++) {
            int j = jb + jj;
            ulonglong2 g01 = *(const ulonglong2*)(Gh + j * 8);
            ulonglong2 g23 = *(const ulonglong2*)(Gh + j * 8 + 4);
            int bi = base_idx - jj;
            #pragma unroll
            for (int k = 0; k < 4; k++) {
                unsigned long long ev = pack2(se[bi + 32 * k]);
                fma2(acc[k][0], ev, g01.x);
                fma2(acc[k][1], ev, g01.y);
                fma2(acc[k][2], ev, g23.x);
                fma2(acc[k][3], ev, g23.y);
            }
        }
    }

    __shared__ __align__(16) float sacc[4][128][8];
    #pragma unroll
    for (int k = 0; k < 4; k++) {
        float2 p0 = unpack2(acc[k][0]);
        float2 p1 = unpack2(acc[k][1]);
        float2 p2 = unpack2(acc[k][2]);
        float2 p3 = unpack2(acc[k][3]);
        *(float4*)&sacc[w][lane + 32 * k][0] = make_float4(p0.x, p0.y, p1.x, p1.y);
        *(float4*)&sacc[w][lane + 32 * k][4] = make_float4(p2.x, p2.y, p3.x, p3.y);
    }
    __syncthreads();

    int l = lbase + t;
    if (l < Lc - 1) {
        float zi = d_zinv[l * Hc + h];
        #pragma unroll
        for (int b = 0; b < 8; b++) {
            float v = sacc[0][t][b] + sacc[1][t][b] + sacc[2][t][b] + sacc[3][t][b];
            atomicAdd(&d_scores[b * Lc + l], v * zi);
        }
    }
}

// ---------------- K5: fused softmax stats + out ------------------------------
// grid (L/64, B), block 128. Batch-32 loads.
__global__ void __launch_bounds__(128) k_out(const float* __restrict__ x,
                                             float* __restrict__ out) {
    int lbase = blockIdx.x * 64;
    int b = blockIdx.y;
    int t = threadIdx.x;
    const float* sc = d_scores + b * Lc;

    __shared__ float red[128];
    float m = -1e30f;
    for (int l = t; l < Lc - 1; l += 128) m = fmaxf(m, sc[l]);
    red[t] = m; __syncthreads();
    for (int o = 64; o > 0; o >>= 1) {
        if (t < o) red[t] = fmaxf(red[t], red[t + o]);
        __syncthreads();
    }
    float M = red[0]; __syncthreads();
    float ss = 0.f;
    for (int l = t; l < Lc - 1; l += 128) ss += expf(sc[l] - M);
    red[t] = ss; __syncthreads();
    for (int o = 64; o > 0; o >>= 1) {
        if (t < o) red[t] += red[t + o];
        __syncthreads();
    }
    float sinv = 1.f / red[0];
    __syncthreads();

    __shared__ float wsm[64];
    if (t < 64) {
        int lg = lbase + t;
        wsm[t] = (lg < Lc - 1) ? expf(sc[lg] - M) * sinv : 0.f;
    }
    __syncthreads();

    float acc = 0.f;
    const float* xp = x + ((size_t)b * Lc + lbase) * Sc + t;
    #pragma unroll
    for (int j0 = 0; j0 < 64; j0 += 32) {
        float xv[32];
        #pragma unroll
        for (int k = 0; k < 32; k++) xv[k] = xp[(j0 + k) * Sc];
        #pragma unroll
        for (int k = 0; k < 32; k++) acc += wsm[j0 + k] * xv[k];
    }
    atomicAdd(&out[b * Sc + t], acc);
}

// ---------------- launch ----------------------------------------------------
extern "C" void kernel_launch(void* const* d_in, const int* in_sizes, int n_in,
                              void* d_out, int out_size) {
    const float *x = nullptr, *W = nullptr, *A = nullptr;
    for (int i = 0; i < n_in; i++) {
        if (in_sizes[i] == Bc * Lc * Sc)      x = (const float*)d_in[i];
        else if (in_sizes[i] == Lc * Hc)      W = (const float*)d_in[i];
        else if (in_sizes[i] == HSc * HSc)    A = (const float*)d_in[i];
    }
    float* out = (float*)d_out;

    k_init<<<24, 1024>>>(W, out);
    k_q<<<dim3(Lc / 32, Bc), 128>>>(x);
    k_u<<<dim3(HSc / 256, 32), 256>>>(A);
    k_G<<<dim3(Lc / 64, 2, Bc), 256>>>(x);
    k_scores<<<dim3(Lc / 128, 8, Hc), 128>>>();
    k_out<<<dim3(Lc / 64, Bc), 128>>>(x, out);
}